// round 5
// baseline (speedup 1.0000x reference)
#include <cuda_runtime.h>
#include <cuda_bf16.h>

#define NUM_GRAPHS   2048
#define MAX_ATOMS    200000
#define PACK_BLOCKS  148     // <= SM count; guaranteed resident in wave 1
#define THREADS      256

// Packed per-atom tag: (batch << 4) | z.  batch < 2048 (11 bits), z in 1..10 (4 bits).
__device__ unsigned short g_bz[MAX_ATOMS];
__device__ int g_cnt[NUM_GRAPHS];   // running atom counts per graph
__device__ int g_maxd;              // max graph size (prefilter radius)
__device__ int g_done;              // pack-phase completion counter

// Kernel 1: zero output + counters + flags (re-run on every graph replay)
__global__ void init_kernel(float* __restrict__ out, int out_n) {
    int i = blockIdx.x * blockDim.x + threadIdx.x;
    if (i < out_n)      out[i]   = 0.0f;
    if (i < NUM_GRAPHS) g_cnt[i] = 0;
    if (i == 0) { g_maxd = 1; g_done = 0; }
}

// Kernel 2 (fused): pack tags + maxd on blocks 0..147, device-wide release,
// then all blocks stream edges with the gather-free |s-d| < D prefilter.
__global__ void fused_kernel(const float* __restrict__ pos,
                             const float* __restrict__ arep,
                             const float* __restrict__ zeff,
                             const int*   __restrict__ z,
                             const int*   __restrict__ batch,
                             const int*   __restrict__ src_idx,
                             const int*   __restrict__ dst_idx,
                             float*       __restrict__ out,
                             int n_atoms,
                             int n_units,    // number of 8-edge units
                             int n_rem)      // leftover edges (< 8)
{
    const float AA2AU   = 1.8897261258369282f;
    const float AU2KCAL = 627.5094740630558f;

    __shared__ int s_red[THREADS];
    __shared__ int s_D;

    // ---- Phase 1: pack (batch,z) tags + compute max graph size ----
    if (blockIdx.x < PACK_BLOCKS) {
        int local_max = 0;
        for (int i = blockIdx.x * THREADS + threadIdx.x; i < n_atoms;
             i += PACK_BLOCKS * THREADS) {
            int b = batch[i];
            g_bz[i] = (unsigned short)((b << 4) | z[i]);
            int rc = atomicAdd(&g_cnt[b], 1) + 1;   // running count
            local_max = max(local_max, rc);          // max running count == graph size
        }
        s_red[threadIdx.x] = local_max;
        __syncthreads();
        for (int s = THREADS / 2; s > 0; s >>= 1) {
            if ((int)threadIdx.x < s)
                s_red[threadIdx.x] = max(s_red[threadIdx.x], s_red[threadIdx.x + s]);
            __syncthreads();
        }
        if (threadIdx.x == 0) {
            atomicMax(&g_maxd, s_red[0]);
            __threadfence();                         // release tag stores + maxd
            atomicAdd(&g_done, 1);
        }
    }

    // ---- Barrier: wait until all PACK_BLOCKS have released ----
    if (threadIdx.x == 0) {
        while (atomicAdd(&g_done, 0) < PACK_BLOCKS) __nanosleep(64);
        s_D = atomicAdd(&g_maxd, 0);                 // L2-coherent read of D
    }
    __syncthreads();
    const int D = s_D;                               // same-graph => |s-d| < D

    // ---- Phase 2: edge stream, 8 edges / thread (2x int4 per stream) ----
    int t = blockIdx.x * blockDim.x + threadIdx.x;
    if (t < n_units) {
        const int4* s4p = (const int4*)src_idx;
        const int4* d4p = (const int4*)dst_idx;
        int4 sa = s4p[2 * t];
        int4 sb = s4p[2 * t + 1];
        int4 da = d4p[2 * t];
        int4 db = d4p[2 * t + 1];
        const int ss[8] = {sa.x, sa.y, sa.z, sa.w, sb.x, sb.y, sb.z, sb.w};
        const int dd[8] = {da.x, da.y, da.z, da.w, db.x, db.y, db.z, db.w};
        #pragma unroll
        for (int k = 0; k < 8; k++) {
            int s = ss[k];
            int d = dd[k];
            if (abs(s - d) < D) {                    // register-only prefilter
                unsigned short bs = __ldg(&g_bz[s]);
                unsigned short bd = __ldg(&g_bz[d]);
                if ((bs >> 4) == (bd >> 4)) {        // exact same-graph check
                    float psx = __ldg(&pos[3 * s + 0]);
                    float psy = __ldg(&pos[3 * s + 1]);
                    float psz = __ldg(&pos[3 * s + 2]);
                    float pdx = __ldg(&pos[3 * d + 0]);
                    float pdy = __ldg(&pos[3 * d + 1]);
                    float pdz = __ldg(&pos[3 * d + 2]);
                    float dx = psx - pdx, dy = psy - pdy, dz = psz - pdz;
                    float d2 = dx * dx + dy * dy + dz * dz;
                    if (d2 <= 9.0f) {
                        float dist = fmaxf(sqrtf(d2), 1e-9f);
                        float dau  = dist * AA2AU;
                        int zs = bs & 15, zd = bd & 15;
                        float at  = sqrtf(__ldg(&arep[zs]) * __ldg(&arep[zd]));
                        float rep = __ldg(&zeff[zs]) * __ldg(&zeff[zd]) *
                                    expf(-at * dau * sqrtf(dau)) / dau;
                        atomicAdd(&out[bs >> 4], rep * AU2KCAL);
                    }
                }
            }
        }
    }

    // Scalar tail (edges not covered by 8-edge units)
    if (blockIdx.x == 0 && (int)threadIdx.x < n_rem) {
        int e = n_units * 8 + threadIdx.x;
        int s = src_idx[e];
        int d = dst_idx[e];
        if (abs(s - d) < D) {
            unsigned short bs = g_bz[s];
            unsigned short bd = g_bz[d];
            if ((bs >> 4) == (bd >> 4)) {
                float dx = pos[3 * s + 0] - pos[3 * d + 0];
                float dy = pos[3 * s + 1] - pos[3 * d + 1];
                float dz = pos[3 * s + 2] - pos[3 * d + 2];
                float d2 = dx * dx + dy * dy + dz * dz;
                if (d2 <= 9.0f) {
                    float dist = fmaxf(sqrtf(d2), 1e-9f);
                    float dau  = dist * AA2AU;
                    int zs = bs & 15, zd = bd & 15;
                    float at  = sqrtf(arep[zs] * arep[zd]);
                    float rep = zeff[zs] * zeff[zd] *
                                expf(-at * dau * sqrtf(dau)) / dau;
                    atomicAdd(&out[bs >> 4], rep * AU2KCAL);
                }
            }
        }
    }
}

extern "C" void kernel_launch(void* const* d_in, const int* in_sizes, int n_in,
                              void* d_out, int out_size) {
    const float* pos        = (const float*)d_in[0];
    const float* arep       = (const float*)d_in[1];
    const float* zeff       = (const float*)d_in[2];
    const int*   z          = (const int*)d_in[3];
    const int*   edge_index = (const int*)d_in[4];
    const int*   batch      = (const int*)d_in[5];
    float*       out        = (float*)d_out;

    int n_atoms = in_sizes[3];
    int n_edges = in_sizes[4] / 2;
    const int* src_idx = edge_index;
    const int* dst_idx = edge_index + n_edges;

    // 1) zero output + counters + sync state
    int init_n = out_size > NUM_GRAPHS ? out_size : NUM_GRAPHS;
    init_kernel<<<(init_n + THREADS - 1) / THREADS, THREADS>>>(out, out_size);

    // 2) fused pack + barrier + edge stream
    int n_units = n_edges / 8;
    int n_rem   = n_edges - n_units * 8;
    int blocks  = (n_units + THREADS - 1) / THREADS;
    if (blocks < PACK_BLOCKS) blocks = PACK_BLOCKS;
    fused_kernel<<<blocks, THREADS>>>(pos, arep, zeff, z, batch,
                                      src_idx, dst_idx, out,
                                      n_atoms, n_units, n_rem);
}

// round 8
// speedup vs baseline: 1.2341x; 1.2341x over previous
#include <cuda_runtime.h>
#include <cuda_bf16.h>

#define NUM_GRAPHS 2048
#define MAX_ATOMS  200000
#define THREADS    256

// Packed per-atom tag: (batch << 4) | z.  batch < 2048 (11 bits), z in 1..10 (4 bits).
__device__ unsigned short g_bz[MAX_ATOMS];
__device__ int g_cnt[NUM_GRAPHS];   // running atom counts per graph
__device__ int g_maxd;              // max graph size (prefilter radius)

// Kernel 1: zero output + counters + maxd (re-run on every graph replay)
__global__ void init_kernel(float* __restrict__ out, int out_n) {
    int i = blockIdx.x * blockDim.x + threadIdx.x;
    if (i < out_n)      out[i]   = 0.0f;
    if (i < NUM_GRAPHS) g_cnt[i] = 0;
    if (i == 0)         g_maxd   = 1;
}

// Kernel 2: pack tags + max graph size via running-count trick.
// max over i of (running count of batch[i]) == max graph size.
__global__ void pack_tags_kernel(const int* __restrict__ z,
                                 const int* __restrict__ batch,
                                 int n_atoms) {
    int i = blockIdx.x * blockDim.x + threadIdx.x;
    int rc = 0;
    if (i < n_atoms) {
        int b = batch[i];
        g_bz[i] = (unsigned short)((b << 4) | z[i]);
        rc = atomicAdd(&g_cnt[b], 1) + 1;
    }
    // warp max-reduce, one atomicMax per warp
    #pragma unroll
    for (int off = 16; off > 0; off >>= 1)
        rc = max(rc, __shfl_down_sync(0xffffffffu, rc, off));
    if ((threadIdx.x & 31) == 0 && rc > 1)
        atomicMax(&g_maxd, rc);
}

// Per-edge body: register-only prefilter |s-d| < D, then exact tag check,
// then rare-path physics (~0.15% of edges pass the prefilter).
#define EDGE_BODY(s, d)                                                        \
    do {                                                                       \
        if (abs((s) - (d)) < D) {                                              \
            unsigned short bs = __ldg(&g_bz[(s)]);                             \
            unsigned short bd = __ldg(&g_bz[(d)]);                             \
            if ((bs >> 4) == (bd >> 4)) {                                      \
                float dx = __ldg(&pos[3 * (s) + 0]) - __ldg(&pos[3 * (d) + 0]);\
                float dy = __ldg(&pos[3 * (s) + 1]) - __ldg(&pos[3 * (d) + 1]);\
                float dz = __ldg(&pos[3 * (s) + 2]) - __ldg(&pos[3 * (d) + 2]);\
                float d2 = dx * dx + dy * dy + dz * dz;                        \
                if (d2 <= 9.0f) {                                              \
                    float dist = fmaxf(sqrtf(d2), 1e-9f);                      \
                    float dau  = dist * 1.8897261258369282f;                   \
                    int zs = bs & 15, zd = bd & 15;                            \
                    float at  = sqrtf(__ldg(&arep[zs]) * __ldg(&arep[zd]));    \
                    float rep = __ldg(&zeff[zs]) * __ldg(&zeff[zd]) *          \
                                expf(-at * dau * sqrtf(dau)) / dau;            \
                    atomicAdd(&out[bs >> 4], rep * 627.5094740630558f);        \
                }                                                              \
            }                                                                  \
        }                                                                      \
    } while (0)

// Kernel 3: main edge stream, 8 edges/thread, explicit int4 regs (no arrays).
__global__ void __launch_bounds__(THREADS)
repulsion_kernel(const float* __restrict__ pos,
                 const float* __restrict__ arep,
                 const float* __restrict__ zeff,
                 const int*   __restrict__ src_idx,
                 const int*   __restrict__ dst_idx,
                 float*       __restrict__ out,
                 int n_units,    // number of 8-edge units
                 int n_rem)      // leftover edges (< 8)
{
    int t = blockIdx.x * blockDim.x + threadIdx.x;
    const int D = g_maxd;   // same-graph => |src-dst| < D (batch is sorted)

    if (t < n_units) {
        const int4* s4p = (const int4*)src_idx;
        const int4* d4p = (const int4*)dst_idx;
        // 4 independent 16B loads up front (MLP = 4)
        int4 sa = s4p[2 * t];
        int4 sb = s4p[2 * t + 1];
        int4 da = d4p[2 * t];
        int4 db = d4p[2 * t + 1];
        EDGE_BODY(sa.x, da.x);
        EDGE_BODY(sa.y, da.y);
        EDGE_BODY(sa.z, da.z);
        EDGE_BODY(sa.w, da.w);
        EDGE_BODY(sb.x, db.x);
        EDGE_BODY(sb.y, db.y);
        EDGE_BODY(sb.z, db.z);
        EDGE_BODY(sb.w, db.w);
    }

    // Scalar tail (edges not covered by 8-edge units)
    if (blockIdx.x == 0 && (int)threadIdx.x < n_rem) {
        int e = n_units * 8 + threadIdx.x;
        int s = src_idx[e];
        int d = dst_idx[e];
        EDGE_BODY(s, d);
    }
}

extern "C" void kernel_launch(void* const* d_in, const int* in_sizes, int n_in,
                              void* d_out, int out_size) {
    const float* pos        = (const float*)d_in[0];
    const float* arep       = (const float*)d_in[1];
    const float* zeff       = (const float*)d_in[2];
    const int*   z          = (const int*)d_in[3];
    const int*   edge_index = (const int*)d_in[4];
    const int*   batch      = (const int*)d_in[5];
    float*       out        = (float*)d_out;

    int n_atoms = in_sizes[3];
    int n_edges = in_sizes[4] / 2;
    const int* src_idx = edge_index;
    const int* dst_idx = edge_index + n_edges;

    // 1) zero output + counters
    int init_n = out_size > NUM_GRAPHS ? out_size : NUM_GRAPHS;
    init_kernel<<<(init_n + THREADS - 1) / THREADS, THREADS>>>(out, out_size);

    // 2) pack tags + max graph size (fused)
    pack_tags_kernel<<<(n_atoms + THREADS - 1) / THREADS, THREADS>>>(z, batch, n_atoms);

    // 3) main edge stream
    int n_units = n_edges / 8;
    int n_rem   = n_edges - n_units * 8;
    int blocks  = (n_units + THREADS - 1) / THREADS;
    if (blocks < 1) blocks = 1;
    repulsion_kernel<<<blocks, THREADS>>>(pos, arep, zeff, src_idx, dst_idx,
                                          out, n_units, n_rem);
}

// round 9
// speedup vs baseline: 1.5120x; 1.2252x over previous
#include <cuda_runtime.h>
#include <cuda_bf16.h>

#define NUM_GRAPHS 2048
#define MAX_ATOMS  200000
#define THREADS    256

// Packed per-atom tag: (batch << 4) | z.  batch < 2048 (11 bits), z in 1..10 (4 bits).
__device__ unsigned short g_bz[MAX_ATOMS];
__device__ int g_cnt[NUM_GRAPHS];   // running atom counts (zero at kernel_launch entry)
__device__ int g_maxd;              // max graph size (0 at entry; pack fills via atomicMax)
__device__ int g_ready;             // edge-kernel block arrival ticket (0 at entry)

// Kernel 1: zero output + pack tags + max graph size (running-count trick:
// max over i of running count of batch[i] == max graph size).
__global__ void pack_tags_kernel(const int* __restrict__ z,
                                 const int* __restrict__ batch,
                                 float* __restrict__ out, int out_n,
                                 int n_atoms) {
    int i = blockIdx.x * blockDim.x + threadIdx.x;
    if (i < out_n) out[i] = 0.0f;          // out zeroed before edge kernel's atomics
    int rc = 0;
    if (i < n_atoms) {
        int b = batch[i];
        g_bz[i] = (unsigned short)((b << 4) | z[i]);
        rc = atomicAdd(&g_cnt[b], 1) + 1;
    }
    #pragma unroll
    for (int off = 16; off > 0; off >>= 1)
        rc = max(rc, __shfl_down_sync(0xffffffffu, rc, off));
    if ((threadIdx.x & 31) == 0 && rc > 0)
        atomicMax(&g_maxd, rc);
}

// Per-edge body: register-only prefilter |s-d| < D, then exact tag check,
// then rare-path physics (~0.15% of edges pass the prefilter).
#define EDGE_BODY(s, d)                                                        \
    do {                                                                       \
        if (abs((s) - (d)) < D) {                                              \
            unsigned short bs = __ldg(&g_bz[(s)]);                             \
            unsigned short bd = __ldg(&g_bz[(d)]);                             \
            if ((bs >> 4) == (bd >> 4)) {                                      \
                float dx = __ldg(&pos[3 * (s) + 0]) - __ldg(&pos[3 * (d) + 0]);\
                float dy = __ldg(&pos[3 * (s) + 1]) - __ldg(&pos[3 * (d) + 1]);\
                float dz = __ldg(&pos[3 * (s) + 2]) - __ldg(&pos[3 * (d) + 2]);\
                float d2 = dx * dx + dy * dy + dz * dz;                        \
                if (d2 <= 9.0f) {                                              \
                    float dist = fmaxf(sqrtf(d2), 1e-9f);                      \
                    float dau  = dist * 1.8897261258369282f;                   \
                    int zs = bs & 15, zd = bd & 15;                            \
                    float at  = sqrtf(__ldg(&arep[zs]) * __ldg(&arep[zd]));    \
                    float rep = __ldg(&zeff[zs]) * __ldg(&zeff[zd]) *          \
                                expf(-at * dau * sqrtf(dau)) / dau;            \
                    atomicAdd(&out[bs >> 4], rep * 627.5094740630558f);        \
                }                                                              \
            }                                                                  \
        }                                                                      \
    } while (0)

// Kernel 2: main edge stream. 8 edges/thread as two COALESCED int4 quads
// (quad t and quad t+half — unit stride across the warp for every load).
// Last-arriving block resets device state for the next graph replay.
__global__ void __launch_bounds__(THREADS)
repulsion_kernel(const float* __restrict__ pos,
                 const float* __restrict__ arep,
                 const float* __restrict__ zeff,
                 const int*   __restrict__ src_idx,
                 const int*   __restrict__ dst_idx,
                 float*       __restrict__ out,
                 int n_quads,    // number of 4-edge quads
                 int half,       // first-half quad count
                 int n_rem)      // leftover edges (< 4)
{
    __shared__ int s_D;
    __shared__ int s_last;

    // Read D once per block BEFORE joining the ticket, so the resetter can
    // never clobber g_maxd before this block has read it.
    if (threadIdx.x == 0) {
        s_D = g_maxd;
        int arrived = atomicAdd(&g_ready, 1);
        s_last = (arrived == (int)gridDim.x - 1);
    }
    __syncthreads();
    const int D = s_D;     // same-graph => |src-dst| < D (batch is sorted)

    // Last block restores the zero state for the next replay (no one else
    // reads g_cnt/g_maxd/g_ready in this kernel; kernel boundary publishes).
    if (s_last) {
        for (int i = threadIdx.x; i < NUM_GRAPHS; i += THREADS) g_cnt[i] = 0;
        if (threadIdx.x == 0) { g_maxd = 0; g_ready = 0; }
    }

    int t = blockIdx.x * blockDim.x + threadIdx.x;
    const int4* s4p = (const int4*)src_idx;
    const int4* d4p = (const int4*)dst_idx;

    if (t < half) {
        // 4 independent, fully-coalesced 16B loads in flight (MLP = 4)
        int4 sa = s4p[t];
        int4 da = d4p[t];
        int t2 = t + half;
        bool has2 = (t2 < n_quads);
        int4 sb = has2 ? s4p[t2] : make_int4(0, 0, 0, 0);
        int4 db = has2 ? d4p[t2] : make_int4(1, 1, 1, 1);  // s!=d, prefilter-safe
        EDGE_BODY(sa.x, da.x);
        EDGE_BODY(sa.y, da.y);
        EDGE_BODY(sa.z, da.z);
        EDGE_BODY(sa.w, da.w);
        if (has2) {
            EDGE_BODY(sb.x, db.x);
            EDGE_BODY(sb.y, db.y);
            EDGE_BODY(sb.z, db.z);
            EDGE_BODY(sb.w, db.w);
        }
    }

    // Scalar tail (edges not covered by quads)
    if (blockIdx.x == 0 && (int)threadIdx.x < n_rem) {
        int e = n_quads * 4 + threadIdx.x;
        int s = src_idx[e];
        int d = dst_idx[e];
        EDGE_BODY(s, d);
    }
}

extern "C" void kernel_launch(void* const* d_in, const int* in_sizes, int n_in,
                              void* d_out, int out_size) {
    const float* pos        = (const float*)d_in[0];
    const float* arep       = (const float*)d_in[1];
    const float* zeff       = (const float*)d_in[2];
    const int*   z          = (const int*)d_in[3];
    const int*   edge_index = (const int*)d_in[4];
    const int*   batch      = (const int*)d_in[5];
    float*       out        = (float*)d_out;

    int n_atoms = in_sizes[3];
    int n_edges = in_sizes[4] / 2;
    const int* src_idx = edge_index;
    const int* dst_idx = edge_index + n_edges;

    // 1) pack tags + zero output + max graph size (single kernel)
    int pack_n = n_atoms > out_size ? n_atoms : out_size;
    pack_tags_kernel<<<(pack_n + THREADS - 1) / THREADS, THREADS>>>(
        z, batch, out, out_size, n_atoms);

    // 2) main edge stream (8 edges/thread, coalesced split halves)
    int n_quads = n_edges / 4;
    int n_rem   = n_edges - n_quads * 4;
    int half    = (n_quads + 1) / 2;
    int blocks  = (half + THREADS - 1) / THREADS;
    if (blocks < 1) blocks = 1;
    repulsion_kernel<<<blocks, THREADS>>>(pos, arep, zeff, src_idx, dst_idx,
                                          out, n_quads, half, n_rem);
}